// round 9
// baseline (speedup 1.0000x reference)
#include <cuda_runtime.h>
#include <cuda_bf16.h>
#include <math.h>
#include <stdint.h>

// Problem constants
#define DMODEL 768
#define FFND   3072
#define SEQ    2048
#define BATCH  2
#define NTOK   4096
#define NHEAD  12
#define HDIM   64

typedef __nv_bfloat16 bf16;

// ---------------------------------------------------------------------------
// Scratch (__device__ globals; no allocations allowed)
// ---------------------------------------------------------------------------
__device__ float g_p [NTOK * DMODEL];
__device__ float g_p2[NTOK * DMODEL];
__device__ float g_p3[NTOK * DMODEL];
__device__ float g_x1[NTOK * DMODEL];
__device__ float g_f [NTOK * DMODEL];
__device__ float g_f2[NTOK * DMODEL];
__device__ float g_f3[NTOK * DMODEL];
__device__ float g_zero[DMODEL];          // zero-initialized, never written

__device__ bf16 g_xh [NTOK * DMODEL], g_xl [NTOK * DMODEL];
__device__ bf16 g_qh [NTOK * DMODEL], g_ql [NTOK * DMODEL];
__device__ bf16 g_kh [NTOK * DMODEL], g_kl [NTOK * DMODEL];
__device__ bf16 g_vh [NTOK * DMODEL], g_vl [NTOK * DMODEL];
__device__ bf16 g_ah [NTOK * DMODEL], g_al [NTOK * DMODEL];
__device__ bf16 g_x1h[NTOK * DMODEL], g_x1l[NTOK * DMODEL];
__device__ bf16 g_hh [NTOK * FFND],   g_hl [NTOK * FFND];
__device__ bf16 g_Wqh[DMODEL*DMODEL], g_Wql[DMODEL*DMODEL];
__device__ bf16 g_Wkh[DMODEL*DMODEL], g_Wkl[DMODEL*DMODEL];
__device__ bf16 g_Wvh[DMODEL*DMODEL], g_Wvl[DMODEL*DMODEL];
__device__ bf16 g_Woh[DMODEL*DMODEL], g_Wol[DMODEL*DMODEL];
__device__ bf16 g_W1h[FFND*DMODEL],   g_W1l[FFND*DMODEL];
__device__ bf16 g_W2h[DMODEL*FFND],   g_W2l[DMODEL*FFND];

// ---------------------------------------------------------------------------
// PTX helpers (sm_103 base target safe)
// ---------------------------------------------------------------------------
__device__ __forceinline__ uint32_t smem_u32(const void* p) {
    uint32_t a;
    asm("{ .reg .u64 t; cvta.to.shared.u64 t, %1; cvt.u32.u64 %0, t; }"
        : "=r"(a) : "l"(p));
    return a;
}

#define CP16(dst, src) \
    asm volatile("cp.async.cg.shared.global [%0], [%1], 16;" :: "r"(dst), "l"(src))
#define CP_COMMIT() asm volatile("cp.async.commit_group;" ::: "memory")
#define CP_WAIT0()  asm volatile("cp.async.wait_group 0;" ::: "memory")
#define CP_WAIT1()  asm volatile("cp.async.wait_group 1;" ::: "memory")

__device__ __forceinline__ void ldsm4(uint32_t a, uint32_t& r0, uint32_t& r1,
                                      uint32_t& r2, uint32_t& r3) {
    asm volatile("ldmatrix.sync.aligned.m8n8.x4.shared.b16 {%0,%1,%2,%3}, [%4];"
                 : "=r"(r0), "=r"(r1), "=r"(r2), "=r"(r3) : "r"(a));
}
__device__ __forceinline__ void ldsm4t(uint32_t a, uint32_t& r0, uint32_t& r1,
                                       uint32_t& r2, uint32_t& r3) {
    asm volatile("ldmatrix.sync.aligned.m8n8.x4.trans.shared.b16 {%0,%1,%2,%3}, [%4];"
                 : "=r"(r0), "=r"(r1), "=r"(r2), "=r"(r3) : "r"(a));
}

__device__ __forceinline__ void mma16816(float* d, const uint32_t* a,
                                         uint32_t b0, uint32_t b1) {
    asm volatile("mma.sync.aligned.m16n8k16.row.col.f32.bf16.bf16.f32 "
                 "{%0,%1,%2,%3}, {%4,%5,%6,%7}, {%8,%9}, {%0,%1,%2,%3};"
                 : "+f"(d[0]), "+f"(d[1]), "+f"(d[2]), "+f"(d[3])
                 : "r"(a[0]), "r"(a[1]), "r"(a[2]), "r"(a[3]), "r"(b0), "r"(b1));
}

// fast exp2
__device__ __forceinline__ float fexp2(float x) {
    float y;
    asm("ex2.approx.f32 %0, %1;" : "=f"(y) : "f"(x));
    return y;
}

// split two floats -> packed bf16x2 (hi) and bf16x2 (lo), 1-instr packing
__device__ __forceinline__ void split2(float a, float b, uint32_t& hi, uint32_t& lo) {
    asm("cvt.rn.bf16x2.f32 %0, %1, %2;" : "=r"(hi) : "f"(b), "f"(a));
    float ha = __uint_as_float(hi << 16);
    float hb = __uint_as_float(hi & 0xffff0000u);
    asm("cvt.rn.bf16x2.f32 %0, %1, %2;" : "=r"(lo) : "f"(b - hb), "f"(a - ha));
}

// ---------------------------------------------------------------------------
// Merged split conversion, MLP=4: each thread loads 4 independent float4s.
// Block = 1024 float4 = 4096 elems.
// ---------------------------------------------------------------------------
#define CB_X   (NTOK*DMODEL/4096)           // 768
#define CB_W   (DMODEL*DMODEL/4096)         // 144
#define CB_F   (FFND*DMODEL/4096)           // 576
#define CB_TOTAL (CB_X + 4*CB_W + 2*CB_F)   // 2496

__global__ void __launch_bounds__(256) cvt_all_kernel(
    const float* __restrict__ x,
    const float* __restrict__ Wq, const float* __restrict__ Wk,
    const float* __restrict__ Wv, const float* __restrict__ Wo,
    const float* __restrict__ W1, const float* __restrict__ W2,
    bf16* __restrict__ xh,  bf16* __restrict__ xl,
    bf16* __restrict__ Wqh, bf16* __restrict__ Wql,
    bf16* __restrict__ Wkh, bf16* __restrict__ Wkl,
    bf16* __restrict__ Wvh, bf16* __restrict__ Wvl,
    bf16* __restrict__ Woh, bf16* __restrict__ Wol,
    bf16* __restrict__ W1h, bf16* __restrict__ W1l,
    bf16* __restrict__ W2h, bf16* __restrict__ W2l)
{
    int bi = blockIdx.x;
    const float* in; bf16 *hi, *lo; int base;
    if      (bi < CB_X)            { in = x;  hi = xh;  lo = xl;  base = 0; }
    else if (bi < CB_X + CB_W)     { in = Wq; hi = Wqh; lo = Wql; base = CB_X; }
    else if (bi < CB_X + 2*CB_W)   { in = Wk; hi = Wkh; lo = Wkl; base = CB_X + CB_W; }
    else if (bi < CB_X + 3*CB_W)   { in = Wv; hi = Wvh; lo = Wvl; base = CB_X + 2*CB_W; }
    else if (bi < CB_X + 4*CB_W)   { in = Wo; hi = Woh; lo = Wol; base = CB_X + 3*CB_W; }
    else if (bi < CB_X + 4*CB_W + CB_F)
                                   { in = W1; hi = W1h; lo = W1l; base = CB_X + 4*CB_W; }
    else                           { in = W2; hi = W2h; lo = W2l; base = CB_X + 4*CB_W + CB_F; }

    size_t e0 = (size_t)(bi - base) * 1024 + threadIdx.x;   // float4 index
    const float4* in4 = (const float4*)in;
    float4 v[4];
    #pragma unroll
    for (int j = 0; j < 4; j++) v[j] = in4[e0 + j * 256];   // 4 independent loads
    #pragma unroll
    for (int j = 0; j < 4; j++) {
        uint32_t h0, l0, h1, l1;
        split2(v[j].x, v[j].y, h0, l0);
        split2(v[j].z, v[j].w, h1, l1);
        size_t idx = (e0 + (size_t)j * 256) * 4;
        *(uint2*)(hi + idx) = make_uint2(h0, h1);
        *(uint2*)(lo + idx) = make_uint2(l0, l1);
    }
}

// ---------------------------------------------------------------------------
// Shared GEMM body: 128x128 tile, BK=32 (64B rows), 8 warps, 3-stage cp.async
// pipeline, 2 CTAs/SM. 3 MMA terms (hh, hl, lh).
// Fragment pipeline: B double-buffered across the FULL kt (8 tiles, crosses
// the k16 boundary); A reloaded at t=0 and t=4. MMAs interleaved to
// dependency-distance-4 accumulator chains.
// ---------------------------------------------------------------------------
#define GSTAGE 32768                       // 4 matrices x 8KB
#define GSMEM_BYTES (3*GSTAGE + 1024)      // 99328 -> 2 CTA/SM

template<int MODE>
__device__ __forceinline__ void gemm_body(
    const bf16* __restrict__ Ah, const bf16* __restrict__ Al,
    const bf16* __restrict__ Bh, const bf16* __restrict__ Bl,
    const float* __restrict__ bias,
    float* __restrict__ C, bf16* __restrict__ Ch, bf16* __restrict__ Cl,
    int N, int ldk, int kIter, int k0, float scale, int m0, int n0)
{
    extern __shared__ __align__(1024) char smem_raw[];
    uint32_t sb = smem_u32(smem_raw);
    sb = (sb + 1023) & ~1023u;

    const int tid  = threadIdx.x;
    const int lane = tid & 31, wid = tid >> 5;
    const int wm = wid & 3, wn = wid >> 2;

    float acc[2][8][4];
    #pragma unroll
    for (int i = 0; i < 2; i++)
        #pragma unroll
        for (int j = 0; j < 8; j++)
            #pragma unroll
            for (int q = 0; q < 4; q++) acc[i][j][q] = 0.f;

    const int lrow = tid >> 1;
    const int c2   = (tid & 1) * 2;
    const bf16* pAh = Ah + (size_t)(m0 + lrow) * ldk + k0;
    const bf16* pAl = Al + (size_t)(m0 + lrow) * ldk + k0;
    const bf16* pBh = Bh + (size_t)(n0 + lrow) * ldk + k0;
    const bf16* pBl = Bl + (size_t)(n0 + lrow) * ldk + k0;
    const uint32_t swr = (uint32_t)((lrow >> 1) & 3);

    auto load_stage = [&](int s, int kt) {
        uint32_t st = sb + s * GSTAGE + lrow * 64;
        size_t ko = (size_t)kt * 32;
        #pragma unroll
        for (int cc = 0; cc < 2; cc++) {
            int c = c2 + cc;
            uint32_t off = (uint32_t)((c ^ swr) << 4);
            CP16(st + off,         pAh + ko + c * 8);
            CP16(st + 8192 + off,  pAl + ko + c * 8);
            CP16(st + 16384 + off, pBh + ko + c * 8);
            CP16(st + 24576 + off, pBl + ko + c * 8);
        }
    };

    const int nk = kIter >> 5;       // k32 tiles, always >= 4 here
    load_stage(0, 0); CP_COMMIT();
    load_stage(1, 1); CP_COMMIT();

    const int l15 = lane & 15, lh = lane >> 4;
    const int arowbase = wm * 32 + l15;
    const int browbase = wn * 64 + l15;
    int slot = 0, nslot = 2;

    uint32_t ah[2][4], al[2][4];        // A frags, current ks
    uint32_t bh[2][4], bl[2][4];        // B frags, double-buffered

    auto loadA = [&](uint32_t st, int ks) {
        const int chunk = ks * 2 + lh;
        #pragma unroll
        for (int mi = 0; mi < 2; mi++) {
            int row = arowbase + mi * 16;
            uint32_t ad = st + row * 64 + ((chunk ^ ((row >> 1) & 3)) << 4);
            ldsm4(ad,        ah[mi][0], ah[mi][1], ah[mi][2], ah[mi][3]);
            ldsm4(ad + 8192, al[mi][0], al[mi][1], al[mi][2], al[mi][3]);
        }
    };
    auto loadB = [&](uint32_t st, int t, int buf) {
        const int chunk = (t >> 2) * 2 + lh;
        int row = browbase + (t & 3) * 16;
        uint32_t bd = st + 16384 + row * 64 + ((chunk ^ ((row >> 1) & 3)) << 4);
        ldsm4(bd,        bh[buf][0], bh[buf][1], bh[buf][2], bh[buf][3]);
        ldsm4(bd + 8192, bl[buf][0], bl[buf][1], bl[buf][2], bl[buf][3]);
    };

    for (int kt = 0; kt < nk; kt++) {
        if (kt + 1 < nk) CP_WAIT1(); else CP_WAIT0();
        __syncthreads();
        if (kt + 2 < nk) {
            load_stage(nslot, kt + 2);
            CP_COMMIT();
        }
        uint32_t st = sb + slot * GSTAGE;

        loadA(st, 0);
        loadB(st, 0, 0);
        #pragma unroll
        for (int t = 0; t < 8; t++) {
            const int cur = t & 1;
            const int g = t & 3;
            if (t == 4) loadA(st, 1);
            if (t < 7) loadB(st, t + 1, cur ^ 1);
            // interleaved: chains of 3 per accumulator at distance 4
            mma16816(acc[0][2*g],   ah[0], bh[cur][0], bh[cur][2]);
            mma16816(acc[0][2*g+1], ah[0], bh[cur][1], bh[cur][3]);
            mma16816(acc[1][2*g],   ah[1], bh[cur][0], bh[cur][2]);
            mma16816(acc[1][2*g+1], ah[1], bh[cur][1], bh[cur][3]);
            mma16816(acc[0][2*g],   ah[0], bl[cur][0], bl[cur][2]);
            mma16816(acc[0][2*g+1], ah[0], bl[cur][1], bl[cur][3]);
            mma16816(acc[1][2*g],   ah[1], bl[cur][0], bl[cur][2]);
            mma16816(acc[1][2*g+1], ah[1], bl[cur][1], bl[cur][3]);
            mma16816(acc[0][2*g],   al[0], bh[cur][0], bh[cur][2]);
            mma16816(acc[0][2*g+1], al[0], bh[cur][1], bh[cur][3]);
            mma16816(acc[1][2*g],   al[1], bh[cur][0], bh[cur][2]);
            mma16816(acc[1][2*g+1], al[1], bh[cur][1], bh[cur][3]);
        }
        slot = (slot == 2) ? 0 : slot + 1;
        nslot = (nslot == 2) ? 0 : nslot + 1;
    }

    const int g4 = lane >> 2, t4 = lane & 3;
    #pragma unroll
    for (int mi = 0; mi < 2; mi++) {
        #pragma unroll
        for (int n = 0; n < 8; n++) {
            int row = m0 + wm * 32 + mi * 16 + g4;
            int col = n0 + wn * 64 + n * 8 + t4 * 2;
            float b0 = bias[col], b1 = bias[col + 1];
            float v00 = acc[mi][n][0] + b0, v01 = acc[mi][n][1] + b1;
            float v10 = acc[mi][n][2] + b0, v11 = acc[mi][n][3] + b1;
            if (MODE == 0) {
                *(float2*)(C + (size_t)row * N + col)       = make_float2(v00, v01);
                *(float2*)(C + (size_t)(row + 8) * N + col) = make_float2(v10, v11);
            } else {
                if (MODE == 1) {
                    v00 *= scale; v01 *= scale; v10 *= scale; v11 *= scale;
                } else {
                    v00 = 0.5f * v00 * (1.0f + erff(v00 * 0.70710678118654752f));
                    v01 = 0.5f * v01 * (1.0f + erff(v01 * 0.70710678118654752f));
                    v10 = 0.5f * v10 * (1.0f + erff(v10 * 0.70710678118654752f));
                    v11 = 0.5f * v11 * (1.0f + erff(v11 * 0.70710678118654752f));
                }
                uint32_t h0, l0, h1, l1;
                split2(v00, v01, h0, l0);
                split2(v10, v11, h1, l1);
                *(uint32_t*)(Ch + (size_t)row * N + col)       = h0;
                *(uint32_t*)(Ch + (size_t)(row + 8) * N + col) = h1;
                *(uint32_t*)(Cl + (size_t)row * N + col)       = l0;
                *(uint32_t*)(Cl + (size_t)(row + 8) * N + col) = l1;
            }
        }
    }
}

template<int MODE>
__global__ void __launch_bounds__(256, 2) gemm_mma(
    const bf16* __restrict__ Ah, const bf16* __restrict__ Al,
    const bf16* __restrict__ Bh, const bf16* __restrict__ Bl,
    const float* __restrict__ bias,
    float* __restrict__ C, bf16* __restrict__ Ch, bf16* __restrict__ Cl,
    int N, int K)
{
    gemm_body<MODE>(Ah, Al, Bh, Bl, bias, C, Ch, Cl, N, K, K, 0, 1.0f,
                    blockIdx.y * 128, blockIdx.x * 128);
}

// Split-K x3 (fp32 output): z=0 -> C0 (+bias), z=1 -> C1, z=2 -> C2.
__global__ void __launch_bounds__(256, 2) gemm_splitk(
    const bf16* __restrict__ Ah, const bf16* __restrict__ Al,
    const bf16* __restrict__ Bh, const bf16* __restrict__ Bl,
    const float* __restrict__ bias,
    float* __restrict__ C0, float* __restrict__ C1, float* __restrict__ C2,
    int N, int K)
{
    int z = blockIdx.z;
    int kh = K / 3;
    float* Cz = (z == 0) ? C0 : (z == 1) ? C1 : C2;
    gemm_body<0>(Ah, Al, Bh, Bl, z ? g_zero : bias, Cz,
                 nullptr, nullptr, N, K, kh, z * kh, 1.0f,
                 blockIdx.y * 128, blockIdx.x * 128);
}

// Combined QKV: blockIdx.z selects weight/bias/output.
// Q pre-scaled by 0.125 * log2(e) so attention runs in the exp2 domain.
#define QSCALE (0.125f * 1.4426950408889634f)
__global__ void __launch_bounds__(256, 2) gemm_qkv(
    const bf16* __restrict__ Ah, const bf16* __restrict__ Al,
    const bf16* __restrict__ Wqh, const bf16* __restrict__ Wql,
    const bf16* __restrict__ Wkh, const bf16* __restrict__ Wkl,
    const bf16* __restrict__ Wvh, const bf16* __restrict__ Wvl,
    const float* __restrict__ bq, const float* __restrict__ bk,
    const float* __restrict__ bv,
    bf16* __restrict__ qh, bf16* __restrict__ ql,
    bf16* __restrict__ kh, bf16* __restrict__ kl,
    bf16* __restrict__ vh, bf16* __restrict__ vl)
{
    int z = blockIdx.z;
    const bf16* Bh = (z == 0) ? Wqh : (z == 1) ? Wkh : Wvh;
    const bf16* Bl = (z == 0) ? Wql : (z == 1) ? Wkl : Wvl;
    const float* bias = (z == 0) ? bq : (z == 1) ? bk : bv;
    bf16* Ch = (z == 0) ? qh : (z == 1) ? kh : vh;
    bf16* Cl = (z == 0) ? ql : (z == 1) ? kl : vl;
    float scale = (z == 0) ? QSCALE : 1.0f;
    gemm_body<1>(Ah, Al, Bh, Bl, bias, nullptr, Ch, Cl,
                 DMODEL, DMODEL, DMODEL, 0, scale,
                 blockIdx.y * 128, blockIdx.x * 128);
}

// ---------------------------------------------------------------------------
// Flash attention via mma.sync bf16 hi/lo split; softmax in exp2 domain.
// ---------------------------------------------------------------------------
#define ASMEM_BYTES (32768 + 2*32768 + 1024)

__global__ void __launch_bounds__(256, 2) attn_mma(
    const bf16* __restrict__ Qh, const bf16* __restrict__ Ql,
    const bf16* __restrict__ Kh, const bf16* __restrict__ Kl,
    const bf16* __restrict__ Vh, const bf16* __restrict__ Vl,
    bf16* __restrict__ Oh, bf16* __restrict__ Ol)
{
    extern __shared__ __align__(1024) char smem_raw[];
    uint32_t sb = smem_u32(smem_raw);
    sb = (sb + 1023) & ~1023u;

    const int tid  = threadIdx.x;
    const int lane = tid & 31, wq = tid >> 5;
    const int l15 = lane & 15, lh = lane >> 4;
    const int g4 = lane >> 2, t4 = lane & 3;
    const int b = blockIdx.z, h = blockIdx.y;
    const int q0 = blockIdx.x * 128;
    const size_t hoff = (size_t)h * HDIM;

    {
        int qrow = tid >> 1;
        int cb = (tid & 1) * 4;
        size_t gidx = ((size_t)(b * SEQ + q0 + qrow)) * DMODEL + hoff;
        uint32_t st = sb + qrow * 128;
        #pragma unroll
        for (int c = 0; c < 4; c++) {
            uint32_t ph = (uint32_t)(((cb + c) ^ (qrow & 7)) << 4);
            CP16(st + ph,         Qh + gidx + (cb + c) * 8);
            CP16(st + 16384 + ph, Ql + gidx + (cb + c) * 8);
        }
    }
    CP_COMMIT();

    const int krow = tid >> 2;
    const int kc0  = (tid & 3) * 2;
    auto load_kv = [&](int s, int kt) {
        uint32_t base = sb + 32768 + s * 32768;
        size_t gidx = ((size_t)(b * SEQ + kt * 64 + krow)) * DMODEL + hoff;
        #pragma unroll
        for (int cc = 0; cc < 2; cc++) {
            int c = kc0 + cc;
            uint32_t off = krow * 128 + ((c ^ (krow & 7)) << 4);
            CP16(base + off,         Kh + gidx + c * 8);
            CP16(base + 8192 + off,  Kl + gidx + c * 8);
            CP16(base + 16384 + off, Vh + gidx + c * 8);
            CP16(base + 24576 + off, Vl + gidx + c * 8);
        }
    };
    load_kv(0, 0);
    CP_COMMIT();

    float m0 = -1e30f, m1 = -1e30f, l0 = 0.f, l1 = 0.f;
    float o[8][4];
    #pragma unroll
    for (int j = 0; j < 8; j++)
        #pragma unroll
        for (int q = 0; q < 4; q++) o[j][q] = 0.f;

    const int NT = SEQ / 64;
    for (int kt = 0; kt < NT; kt++) {
        CP_WAIT0();
        __syncthreads();
        if (kt + 1 < NT) {
            load_kv((kt + 1) & 1, kt + 1);
            CP_COMMIT();
        }

        uint32_t stb = sb + 32768 + (kt & 1) * 32768;

        float s[8][4];
        #pragma unroll
        for (int j = 0; j < 8; j++)
            #pragma unroll
            for (int q = 0; q < 4; q++) s[j][q] = 0.f;

        #pragma unroll
        for (int kc = 0; kc < 4; kc++) {
            const int chunk = kc * 2 + lh;
            int arow = wq * 16 + l15;
            uint32_t aaddr = sb + arow * 128 + ((chunk ^ (arow & 7)) << 4);
            uint32_t qh_[4], ql_[4];
            ldsm4(aaddr,         qh_[0], qh_[1], qh_[2], qh_[3]);
            ldsm4(aaddr + 16384, ql_[0], ql_[1], ql_[2], ql_[3]);
            #pragma unroll
            for (int g = 0; g < 4; g++) {
                int brow = g * 16 + l15;
                uint32_t baddr = stb + brow * 128 + ((chunk ^ (brow & 7)) << 4);
                uint32_t kh_[4], kl_[4];
                ldsm4(baddr,        kh_[0], kh_[1], kh_[2], kh_[3]);
                ldsm4(baddr + 8192, kl_[0], kl_[1], kl_[2], kl_[3]);
                mma16816(s[2*g],   qh_, kh_[0], kh_[2]);
                mma16816(s[2*g+1], qh_, kh_[1], kh_[3]);
                mma16816(s[2*g],   qh_, kl_[0], kl_[2]);
                mma16816(s[2*g+1], qh_, kl_[1], kl_[3]);
                mma16816(s[2*g],   ql_, kh_[0], kh_[2]);
                mma16816(s[2*g+1], ql_, kh_[1], kh_[3]);
            }
        }

        float mx0 = -1e30f, mx1 = -1e30f;
        #pragma unroll
        for (int j = 0; j < 8; j++) {
            mx0 = fmaxf(mx0, fmaxf(s[j][0], s[j][1]));
            mx1 = fmaxf(mx1, fmaxf(s[j][2], s[j][3]));
        }
        mx0 = fmaxf(mx0, __shfl_xor_sync(0xffffffffu, mx0, 1));
        mx0 = fmaxf(mx0, __shfl_xor_sync(0xffffffffu, mx0, 2));
        mx1 = fmaxf(mx1, __shfl_xor_sync(0xffffffffu, mx1, 1));
        mx1 = fmaxf(mx1, __shfl_xor_sync(0xffffffffu, mx1, 2));

        float mn0 = fmaxf(m0, mx0), mn1 = fmaxf(m1, mx1);
        float a0 = fexp2(m0 - mn0), a1 = fexp2(m1 - mn1);
        m0 = mn0; m1 = mn1;

        float sum0 = 0.f, sum1 = 0.f;
        #pragma unroll
        for (int j = 0; j < 8; j++) {
            s[j][0] = fexp2(s[j][0] - mn0);
            s[j][1] = fexp2(s[j][1] - mn0);
            s[j][2] = fexp2(s[j][2] - mn1);
            s[j][3] = fexp2(s[j][3] - mn1);
            sum0 += s[j][0] + s[j][1];
            sum1 += s[j][2] + s[j][3];
        }
        sum0 += __shfl_xor_sync(0xffffffffu, sum0, 1);
        sum0 += __shfl_xor_sync(0xffffffffu, sum0, 2);
        sum1 += __shfl_xor_sync(0xffffffffu, sum1, 1);
        sum1 += __shfl_xor_sync(0xffffffffu, sum1, 2);
        l0 = l0 * a0 + sum0;
        l1 = l1 * a1 + sum1;

        #pragma unroll
        for (int j = 0; j < 8; j++) {
            o[j][0] *= a0; o[j][1] *= a0;
            o[j][2] *= a1; o[j][3] *= a1;
        }

        #pragma unroll
        for (int kc = 0; kc < 4; kc++) {
            uint32_t ph_[4], pl_[4];
            split2(s[2*kc][0],   s[2*kc][1],   ph_[0], pl_[0]);
            split2(s[2*kc][2],   s[2*kc][3],   ph_[1], pl_[1]);
            split2(s[2*kc+1][0], s[2*kc+1][1], ph_[2], pl_[2]);
            split2(s[2*kc+1][2], s[2*kc+1][3], ph_[3], pl_[3]);

            int vrow = kc * 16 + (lane & 7) + ((lane >> 3) & 1) * 8;
            #pragma unroll
            for (int nn = 0; nn < 4; nn++) {
                int colchunk = nn * 2 + (lane >> 4);
                uint32_t vaddr = stb + 16384 + vrow * 128
                               + ((colchunk ^ (vrow & 7)) << 4);
                uint32_t vh_[4], vl_[4];
                ldsm4t(vaddr,        vh_[0], vh_[1], vh_[2], vh_[3]);
                ldsm4t(vaddr + 8192, vl_[0], vl_[1], vl_[2], vl_[3]);
                mma16816(o[2*nn],   ph_, vh_[0], vh_[1]);
                mma16816(o[2*nn+1], ph_, vh_[2], vh_[3]);
                mma16816(o[2*nn],   ph_, vl_[0], vl_[1]);
                mma16816(o[2*nn+1], ph_, vl_[2], vl_[3]);
                mma16816(o[2*nn],   pl_, vh_[0], vh_[1]);
                mma16816(o[2*nn+1], pl_, vh_[2], vh_[3]);
            }
        }
    }

    float i0 = 1.0f / l0, i1 = 1.0f / l1;
    int row0 = b * SEQ + q0 + wq * 16 + g4;
    #pragma unroll
    for (int j = 0; j < 8; j++) {
        int col = (int)hoff + j * 8 + t4 * 2;
        uint32_t h0, lo0, h1, lo1;
        split2(o[j][0] * i0, o[j][1] * i0, h0, lo0);
        split2(o[j][2] * i1, o[j][3] * i1, h1, lo1);
        *(uint32_t*)(Oh + (size_t)row0 * DMODEL + col)       = h0;
        *(uint32_t*)(Ol + (size_t)row0 * DMODEL + col)       = lo0;
        *(uint32_t*)(Oh + (size_t)(row0 + 8) * DMODEL + col) = h1;
        *(uint32_t*)(Ol + (size_t)(row0 + 8) * DMODEL + col) = lo1;
    }
}

// ---------------------------------------------------------------------------
// Fused residual add + LayerNorm over (y0 + y1 + y2 + residual).
// ---------------------------------------------------------------------------
__global__ void __launch_bounds__(256) ln_res_kernel(
    const float* __restrict__ y0, const float* __restrict__ y1,
    const float* __restrict__ y2, const float* __restrict__ r,
    const float* __restrict__ g, const float* __restrict__ b,
    float* __restrict__ o, bf16* __restrict__ oh, bf16* __restrict__ ol)
{
    const int row = blockIdx.x;
    const int tid = threadIdx.x;
    const float* y0p = y0 + (size_t)row * DMODEL;
    const float* y1p = y1 + (size_t)row * DMODEL;
    const float* y2p = y2 + (size_t)row * DMODEL;
    const float* rp  = r  + (size_t)row * DMODEL;

    float v[3];
    float s = 0.f, ss = 0.f;
    #pragma unroll
    for (int j = 0; j < 3; j++) {
        int c = tid + j * 256;
        float a = y0p[c] + y1p[c] + y2p[c] + rp[c];
        v[j] = a; s += a; ss += a * a;
    }
    #pragma unroll
    for (int off = 16; off; off >>= 1) {
        s  += __shfl_xor_sync(0xffffffffu, s, off);
        ss += __shfl_xor_sync(0xffffffffu, ss, off);
    }
    __shared__ float sred[16];
    if ((tid & 31) == 0) { sred[tid >> 5] = s; sred[8 + (tid >> 5)] = ss; }
    __syncthreads();
    if (tid == 0) {
        float S = 0.f, SS = 0.f;
        #pragma unroll
        for (int w = 0; w < 8; w++) { S += sred[w]; SS += sred[8 + w]; }
        sred[0] = S * (1.0f / DMODEL);
        sred[1] = SS * (1.0f / DMODEL);
    }
    __syncthreads();
    float mu  = sred[0];
    float var = sred[1] - mu * mu;
    float rstd = rsqrtf(var + 1e-5f);
    float* op = o + (size_t)row * DMODEL;
    #pragma unroll
    for (int j = 0; j < 3; j++) {
        int c = tid + j * 256;
        float val = (v[j] - mu) * rstd * g[c] + b[c];
        op[c] = val;
        if (oh) {
            bf16 hv = __float2bfloat16(val);
            oh[(size_t)row * DMODEL + c] = hv;
            ol[(size_t)row * DMODEL + c] =
                __float2bfloat16(val - __bfloat162float(hv));
        }
    }
}

// ---------------------------------------------------------------------------
extern "C" void kernel_launch(void* const* d_in, const int* in_sizes, int n_in,
                              void* d_out, int out_size)
{
    const float* x     = (const float*)d_in[0];
    const float* Wq    = (const float*)d_in[1];
    const float* bq    = (const float*)d_in[2];
    const float* Wk    = (const float*)d_in[3];
    const float* bk    = (const float*)d_in[4];
    const float* Wv    = (const float*)d_in[5];
    const float* bv    = (const float*)d_in[6];
    const float* Wo    = (const float*)d_in[7];
    const float* bo    = (const float*)d_in[8];
    const float* ln1g  = (const float*)d_in[9];
    const float* ln1b  = (const float*)d_in[10];
    const float* ln2g  = (const float*)d_in[11];
    const float* ln2b  = (const float*)d_in[12];
    const float* W1    = (const float*)d_in[13];
    const float* b1    = (const float*)d_in[14];
    const float* W2    = (const float*)d_in[15];
    const float* b2    = (const float*)d_in[16];
    float* out = (float*)d_out;

    float *p, *p2, *p3, *x1, *f, *f2, *f3;
    cudaGetSymbolAddress((void**)&p,  g_p);
    cudaGetSymbolAddress((void**)&p2, g_p2);
    cudaGetSymbolAddress((void**)&p3, g_p3);
    cudaGetSymbolAddress((void**)&x1, g_x1);
    cudaGetSymbolAddress((void**)&f,  g_f);
    cudaGetSymbolAddress((void**)&f2, g_f2);
    cudaGetSymbolAddress((void**)&f3, g_f3);

    bf16 *xh,*xl,*qh,*ql,*kh,*kl,*vh,*vl,*ah,*al,*x1h,*x1l,*hh,*hl;
    bf16 *Wqh,*Wql,*Wkh,*Wkl,*Wvh,*Wvl,*Woh,*Wol,*W1h,*W1l,*W2h,*W2l;
    cudaGetSymbolAddress((void**)&xh,  g_xh);  cudaGetSymbolAddress((void**)&xl,  g_xl);
    cudaGetSymbolAddress((void**)&qh,  g_qh);  cudaGetSymbolAddress((void**)&ql,  g_ql);
    cudaGetSymbolAddress((void**)&kh,  g_kh);  cudaGetSymbolAddress((void**)&kl,  g_kl);
    cudaGetSymbolAddress((void**)&vh,  g_vh);  cudaGetSymbolAddress((void**)&vl,  g_vl);
    cudaGetSymbolAddress((void**)&ah,  g_ah);  cudaGetSymbolAddress((void**)&al,  g_al);
    cudaGetSymbolAddress((void**)&x1h, g_x1h); cudaGetSymbolAddress((void**)&x1l, g_x1l);
    cudaGetSymbolAddress((void**)&hh,  g_hh);  cudaGetSymbolAddress((void**)&hl,  g_hl);
    cudaGetSymbolAddress((void**)&Wqh, g_Wqh); cudaGetSymbolAddress((void**)&Wql, g_Wql);
    cudaGetSymbolAddress((void**)&Wkh, g_Wkh); cudaGetSymbolAddress((void**)&Wkl, g_Wkl);
    cudaGetSymbolAddress((void**)&Wvh, g_Wvh); cudaGetSymbolAddress((void**)&Wvl, g_Wvl);
    cudaGetSymbolAddress((void**)&Woh, g_Woh); cudaGetSymbolAddress((void**)&Wol, g_Wol);
    cudaGetSymbolAddress((void**)&W1h, g_W1h); cudaGetSymbolAddress((void**)&W1l, g_W1l);
    cudaGetSymbolAddress((void**)&W2h, g_W2h); cudaGetSymbolAddress((void**)&W2l, g_W2l);

    cudaFuncSetAttribute(gemm_mma<2>,
                         cudaFuncAttributeMaxDynamicSharedMemorySize, GSMEM_BYTES);
    cudaFuncSetAttribute(gemm_splitk,
                         cudaFuncAttributeMaxDynamicSharedMemorySize, GSMEM_BYTES);
    cudaFuncSetAttribute(gemm_qkv,
                         cudaFuncAttributeMaxDynamicSharedMemorySize, GSMEM_BYTES);
    cudaFuncSetAttribute(attn_mma,
                         cudaFuncAttributeMaxDynamicSharedMemorySize, ASMEM_BYTES);

    dim3 blk(256);

    // Merged split conversion, MLP=4
    cvt_all_kernel<<<CB_TOTAL, blk>>>(x, Wq, Wk, Wv, Wo, W1, W2,
                                      xh, xl, Wqh, Wql, Wkh, Wkl, Wvh, Wvl,
                                      Woh, Wol, W1h, W1l, W2h, W2l);

    // QKV combined (bf16 split out; Q pre-scaled by 0.125*log2e)
    dim3 gqkv(DMODEL / 128, NTOK / 128, 3);
    gemm_qkv<<<gqkv, blk, GSMEM_BYTES>>>(xh, xl, Wqh, Wql, Wkh, Wkl, Wvh, Wvl,
                                         bq, bk, bv, qh, ql, kh, kl, vh, vl);

    // Attention (exp2-domain flash attention)
    dim3 ga(SEQ / 128, NHEAD, BATCH);
    attn_mma<<<ga, blk, ASMEM_BYTES>>>(qh, ql, kh, kl, vh, vl, ah, al);

    // Output projection (split-K x3) + residual LN1
    dim3 gS(DMODEL / 128, NTOK / 128, 3);
    gemm_splitk<<<gS, blk, GSMEM_BYTES>>>(ah, al, Woh, Wol, bo, p, p2, p3,
                                          DMODEL, DMODEL);
    ln_res_kernel<<<NTOK, blk>>>(p, p2, p3, x, ln1g, ln1b, x1, x1h, x1l);

    // FFN1 (GELU, bf16 split hidden)
    dim3 gF(FFND / 128, NTOK / 128);
    gemm_mma<2><<<gF, blk, GSMEM_BYTES>>>(x1h, x1l, W1h, W1l, b1,
                                          nullptr, hh, hl, FFND, DMODEL);
    // FFN2 (split-K x3) + residual LN2 -> out
    gemm_splitk<<<gS, blk, GSMEM_BYTES>>>(hh, hl, W2h, W2l, b2, f, f2, f3,
                                          DMODEL, FFND);
    ln_res_kernel<<<NTOK, blk>>>(f, f2, f3, x1, ln2g, ln2b, out, nullptr, nullptr);
}

// round 11
// speedup vs baseline: 1.5024x; 1.5024x over previous
#include <cuda_runtime.h>
#include <cuda_bf16.h>
#include <math.h>
#include <stdint.h>

// Problem constants
#define DMODEL 768
#define FFND   3072
#define SEQ    2048
#define BATCH  2
#define NTOK   4096
#define NHEAD  12
#define HDIM   64

typedef __nv_bfloat16 bf16;

// ---------------------------------------------------------------------------
// Scratch (__device__ globals; no allocations allowed)
// ---------------------------------------------------------------------------
__device__ float g_p [NTOK * DMODEL];
__device__ float g_p2[NTOK * DMODEL];
__device__ float g_p3[NTOK * DMODEL];
__device__ float g_x1[NTOK * DMODEL];
__device__ float g_f [NTOK * DMODEL];
__device__ float g_f2[NTOK * DMODEL];
__device__ float g_f3[NTOK * DMODEL];
__device__ float g_zero[DMODEL];          // zero-initialized, never written

__device__ bf16 g_xh [NTOK * DMODEL], g_xl [NTOK * DMODEL];
__device__ bf16 g_qh [NTOK * DMODEL], g_ql [NTOK * DMODEL];
__device__ bf16 g_kh [NTOK * DMODEL], g_kl [NTOK * DMODEL];
__device__ bf16 g_vh [NTOK * DMODEL], g_vl [NTOK * DMODEL];
__device__ bf16 g_ah [NTOK * DMODEL], g_al [NTOK * DMODEL];
__device__ bf16 g_x1h[NTOK * DMODEL], g_x1l[NTOK * DMODEL];
__device__ bf16 g_hh [NTOK * FFND],   g_hl [NTOK * FFND];
__device__ bf16 g_Wqh[DMODEL*DMODEL], g_Wql[DMODEL*DMODEL];
__device__ bf16 g_Wkh[DMODEL*DMODEL], g_Wkl[DMODEL*DMODEL];
__device__ bf16 g_Wvh[DMODEL*DMODEL], g_Wvl[DMODEL*DMODEL];
__device__ bf16 g_Woh[DMODEL*DMODEL], g_Wol[DMODEL*DMODEL];
__device__ bf16 g_W1h[FFND*DMODEL],   g_W1l[FFND*DMODEL];
__device__ bf16 g_W2h[DMODEL*FFND],   g_W2l[DMODEL*FFND];

// ---------------------------------------------------------------------------
// PTX helpers (sm_103 base target safe)
// ---------------------------------------------------------------------------
__device__ __forceinline__ uint32_t smem_u32(const void* p) {
    uint32_t a;
    asm("{ .reg .u64 t; cvta.to.shared.u64 t, %1; cvt.u32.u64 %0, t; }"
        : "=r"(a) : "l"(p));
    return a;
}

#define CP16(dst, src) \
    asm volatile("cp.async.cg.shared.global [%0], [%1], 16;" :: "r"(dst), "l"(src))
#define CP_COMMIT() asm volatile("cp.async.commit_group;" ::: "memory")
#define CP_WAIT0()  asm volatile("cp.async.wait_group 0;" ::: "memory")
#define CP_WAIT1()  asm volatile("cp.async.wait_group 1;" ::: "memory")

__device__ __forceinline__ void ldsm4(uint32_t a, uint32_t& r0, uint32_t& r1,
                                      uint32_t& r2, uint32_t& r3) {
    asm volatile("ldmatrix.sync.aligned.m8n8.x4.shared.b16 {%0,%1,%2,%3}, [%4];"
                 : "=r"(r0), "=r"(r1), "=r"(r2), "=r"(r3) : "r"(a));
}
__device__ __forceinline__ void ldsm4t(uint32_t a, uint32_t& r0, uint32_t& r1,
                                       uint32_t& r2, uint32_t& r3) {
    asm volatile("ldmatrix.sync.aligned.m8n8.x4.trans.shared.b16 {%0,%1,%2,%3}, [%4];"
                 : "=r"(r0), "=r"(r1), "=r"(r2), "=r"(r3) : "r"(a));
}

__device__ __forceinline__ void mma16816(float* d, const uint32_t* a,
                                         uint32_t b0, uint32_t b1) {
    asm volatile("mma.sync.aligned.m16n8k16.row.col.f32.bf16.bf16.f32 "
                 "{%0,%1,%2,%3}, {%4,%5,%6,%7}, {%8,%9}, {%0,%1,%2,%3};"
                 : "+f"(d[0]), "+f"(d[1]), "+f"(d[2]), "+f"(d[3])
                 : "r"(a[0]), "r"(a[1]), "r"(a[2]), "r"(a[3]), "r"(b0), "r"(b1));
}

// fast exp2
__device__ __forceinline__ float fexp2(float x) {
    float y;
    asm("ex2.approx.f32 %0, %1;" : "=f"(y) : "f"(x));
    return y;
}

// split two floats -> packed bf16x2 (hi) and bf16x2 (lo), 1-instr packing
__device__ __forceinline__ void split2(float a, float b, uint32_t& hi, uint32_t& lo) {
    asm("cvt.rn.bf16x2.f32 %0, %1, %2;" : "=r"(hi) : "f"(b), "f"(a));
    float ha = __uint_as_float(hi << 16);
    float hb = __uint_as_float(hi & 0xffff0000u);
    asm("cvt.rn.bf16x2.f32 %0, %1, %2;" : "=r"(lo) : "f"(b - hb), "f"(a - ha));
}

// ---------------------------------------------------------------------------
// Merged split conversion, MLP=4: each thread loads 4 independent float4s.
// Block = 1024 float4 = 4096 elems.
// ---------------------------------------------------------------------------
#define CB_X   (NTOK*DMODEL/4096)           // 768
#define CB_W   (DMODEL*DMODEL/4096)         // 144
#define CB_F   (FFND*DMODEL/4096)           // 576
#define CB_TOTAL (CB_X + 4*CB_W + 2*CB_F)   // 2496

__global__ void __launch_bounds__(256) cvt_all_kernel(
    const float* __restrict__ x,
    const float* __restrict__ Wq, const float* __restrict__ Wk,
    const float* __restrict__ Wv, const float* __restrict__ Wo,
    const float* __restrict__ W1, const float* __restrict__ W2,
    bf16* __restrict__ xh,  bf16* __restrict__ xl,
    bf16* __restrict__ Wqh, bf16* __restrict__ Wql,
    bf16* __restrict__ Wkh, bf16* __restrict__ Wkl,
    bf16* __restrict__ Wvh, bf16* __restrict__ Wvl,
    bf16* __restrict__ Woh, bf16* __restrict__ Wol,
    bf16* __restrict__ W1h, bf16* __restrict__ W1l,
    bf16* __restrict__ W2h, bf16* __restrict__ W2l)
{
    int bi = blockIdx.x;
    const float* in; bf16 *hi, *lo; int base;
    if      (bi < CB_X)            { in = x;  hi = xh;  lo = xl;  base = 0; }
    else if (bi < CB_X + CB_W)     { in = Wq; hi = Wqh; lo = Wql; base = CB_X; }
    else if (bi < CB_X + 2*CB_W)   { in = Wk; hi = Wkh; lo = Wkl; base = CB_X + CB_W; }
    else if (bi < CB_X + 3*CB_W)   { in = Wv; hi = Wvh; lo = Wvl; base = CB_X + 2*CB_W; }
    else if (bi < CB_X + 4*CB_W)   { in = Wo; hi = Woh; lo = Wol; base = CB_X + 3*CB_W; }
    else if (bi < CB_X + 4*CB_W + CB_F)
                                   { in = W1; hi = W1h; lo = W1l; base = CB_X + 4*CB_W; }
    else                           { in = W2; hi = W2h; lo = W2l; base = CB_X + 4*CB_W + CB_F; }

    size_t e0 = (size_t)(bi - base) * 1024 + threadIdx.x;   // float4 index
    const float4* in4 = (const float4*)in;
    float4 v[4];
    #pragma unroll
    for (int j = 0; j < 4; j++) v[j] = in4[e0 + j * 256];   // 4 independent loads
    #pragma unroll
    for (int j = 0; j < 4; j++) {
        uint32_t h0, l0, h1, l1;
        split2(v[j].x, v[j].y, h0, l0);
        split2(v[j].z, v[j].w, h1, l1);
        size_t idx = (e0 + (size_t)j * 256) * 4;
        *(uint2*)(hi + idx) = make_uint2(h0, h1);
        *(uint2*)(lo + idx) = make_uint2(l0, l1);
    }
}

// ---------------------------------------------------------------------------
// Shared GEMM body (R8-measured structure): 128x128 tile, BK=32 (64B rows),
// 8 warps, 3-stage cp.async pipeline, 2 CTAs/SM. 3 MMA terms (hh, hl, lh).
// A loaded up front per k16 step; B double-buffered within the k16 step
// (prefetch g+1 before consuming g).
// 64B-row swizzle: chunk ^= (row>>1)&3.
// MODE 0: fp32 C + bias.  MODE 1: bf16 split out, (acc+bias)*scale.
// MODE 2: GELU -> bf16 split out.
// ---------------------------------------------------------------------------
#define GSTAGE 32768                       // 4 matrices x 8KB
#define GSMEM_BYTES (3*GSTAGE + 1024)      // 99328 -> 2 CTA/SM

template<int MODE>
__device__ __forceinline__ void gemm_body(
    const bf16* __restrict__ Ah, const bf16* __restrict__ Al,
    const bf16* __restrict__ Bh, const bf16* __restrict__ Bl,
    const float* __restrict__ bias,
    float* __restrict__ C, bf16* __restrict__ Ch, bf16* __restrict__ Cl,
    int N, int ldk, int kIter, int k0, float scale, int m0, int n0)
{
    extern __shared__ __align__(1024) char smem_raw[];
    uint32_t sb = smem_u32(smem_raw);
    sb = (sb + 1023) & ~1023u;

    const int tid  = threadIdx.x;
    const int lane = tid & 31, wid = tid >> 5;
    const int wm = wid & 3, wn = wid >> 2;

    float acc[2][8][4];
    #pragma unroll
    for (int i = 0; i < 2; i++)
        #pragma unroll
        for (int j = 0; j < 8; j++)
            #pragma unroll
            for (int q = 0; q < 4; q++) acc[i][j][q] = 0.f;

    const int lrow = tid >> 1;
    const int c2   = (tid & 1) * 2;
    const bf16* pAh = Ah + (size_t)(m0 + lrow) * ldk + k0;
    const bf16* pAl = Al + (size_t)(m0 + lrow) * ldk + k0;
    const bf16* pBh = Bh + (size_t)(n0 + lrow) * ldk + k0;
    const bf16* pBl = Bl + (size_t)(n0 + lrow) * ldk + k0;
    const uint32_t swr = (uint32_t)((lrow >> 1) & 3);

    auto load_stage = [&](int s, int kt) {
        uint32_t st = sb + s * GSTAGE + lrow * 64;
        size_t ko = (size_t)kt * 32;
        #pragma unroll
        for (int cc = 0; cc < 2; cc++) {
            int c = c2 + cc;
            uint32_t off = (uint32_t)((c ^ swr) << 4);
            CP16(st + off,         pAh + ko + c * 8);
            CP16(st + 8192 + off,  pAl + ko + c * 8);
            CP16(st + 16384 + off, pBh + ko + c * 8);
            CP16(st + 24576 + off, pBl + ko + c * 8);
        }
    };

    const int nk = kIter >> 5;       // k32 tiles, always >= 4 here
    load_stage(0, 0); CP_COMMIT();
    load_stage(1, 1); CP_COMMIT();

    const int l15 = lane & 15, lh = lane >> 4;
    const int arowbase = wm * 32 + l15;
    const int browbase = wn * 64 + l15;
    int slot = 0, nslot = 2;

    for (int kt = 0; kt < nk; kt++) {
        if (kt + 1 < nk) CP_WAIT1(); else CP_WAIT0();
        __syncthreads();
        if (kt + 2 < nk) {
            load_stage(nslot, kt + 2);
            CP_COMMIT();
        }
        uint32_t st = sb + slot * GSTAGE;

        #pragma unroll
        for (int ks = 0; ks < 2; ks++) {
            const int chunk = ks * 2 + lh;
            // ---- load all A fragments for this k16 step ----
            uint32_t ah[2][4], al[2][4];
            #pragma unroll
            for (int mi = 0; mi < 2; mi++) {
                int row = arowbase + mi * 16;
                uint32_t ad = st + row * 64 + ((chunk ^ ((row >> 1) & 3)) << 4);
                ldsm4(ad,        ah[mi][0], ah[mi][1], ah[mi][2], ah[mi][3]);
                ldsm4(ad + 8192, al[mi][0], al[mi][1], al[mi][2], al[mi][3]);
            }
            // ---- B double buffer: prefetch g=0 ----
            uint32_t bh[2][4], bl[2][4];
            {
                uint32_t bd = st + 16384 + browbase * 64
                            + ((chunk ^ ((browbase >> 1) & 3)) << 4);
                ldsm4(bd,        bh[0][0], bh[0][1], bh[0][2], bh[0][3]);
                ldsm4(bd + 8192, bl[0][0], bl[0][1], bl[0][2], bl[0][3]);
            }
            #pragma unroll
            for (int g = 0; g < 4; g++) {
                const int cur = g & 1;
                if (g < 3) {   // prefetch next B before consuming current
                    int row = browbase + (g + 1) * 16;
                    uint32_t bd = st + 16384 + row * 64
                                + ((chunk ^ ((row >> 1) & 3)) << 4);
                    ldsm4(bd,        bh[cur^1][0], bh[cur^1][1],
                                     bh[cur^1][2], bh[cur^1][3]);
                    ldsm4(bd + 8192, bl[cur^1][0], bl[cur^1][1],
                                     bl[cur^1][2], bl[cur^1][3]);
                }
                #pragma unroll
                for (int mi = 0; mi < 2; mi++) {
                    mma16816(acc[mi][2*g],   ah[mi], bh[cur][0], bh[cur][2]);
                    mma16816(acc[mi][2*g],   ah[mi], bl[cur][0], bl[cur][2]);
                    mma16816(acc[mi][2*g],   al[mi], bh[cur][0], bh[cur][2]);
                    mma16816(acc[mi][2*g+1], ah[mi], bh[cur][1], bh[cur][3]);
                    mma16816(acc[mi][2*g+1], ah[mi], bl[cur][1], bl[cur][3]);
                    mma16816(acc[mi][2*g+1], al[mi], bh[cur][1], bh[cur][3]);
                }
            }
        }
        slot = (slot == 2) ? 0 : slot + 1;
        nslot = (nslot == 2) ? 0 : nslot + 1;
    }

    const int g4 = lane >> 2, t4 = lane & 3;
    #pragma unroll
    for (int mi = 0; mi < 2; mi++) {
        #pragma unroll
        for (int n = 0; n < 8; n++) {
            int row = m0 + wm * 32 + mi * 16 + g4;
            int col = n0 + wn * 64 + n * 8 + t4 * 2;
            float b0 = bias[col], b1 = bias[col + 1];
            float v00 = acc[mi][n][0] + b0, v01 = acc[mi][n][1] + b1;
            float v10 = acc[mi][n][2] + b0, v11 = acc[mi][n][3] + b1;
            if (MODE == 0) {
                *(float2*)(C + (size_t)row * N + col)       = make_float2(v00, v01);
                *(float2*)(C + (size_t)(row + 8) * N + col) = make_float2(v10, v11);
            } else {
                if (MODE == 1) {
                    v00 *= scale; v01 *= scale; v10 *= scale; v11 *= scale;
                } else {
                    v00 = 0.5f * v00 * (1.0f + erff(v00 * 0.70710678118654752f));
                    v01 = 0.5f * v01 * (1.0f + erff(v01 * 0.70710678118654752f));
                    v10 = 0.5f * v10 * (1.0f + erff(v10 * 0.70710678118654752f));
                    v11 = 0.5f * v11 * (1.0f + erff(v11 * 0.70710678118654752f));
                }
                uint32_t h0, l0, h1, l1;
                split2(v00, v01, h0, l0);
                split2(v10, v11, h1, l1);
                *(uint32_t*)(Ch + (size_t)row * N + col)       = h0;
                *(uint32_t*)(Ch + (size_t)(row + 8) * N + col) = h1;
                *(uint32_t*)(Cl + (size_t)row * N + col)       = l0;
                *(uint32_t*)(Cl + (size_t)(row + 8) * N + col) = l1;
            }
        }
    }
}

template<int MODE>
__global__ void __launch_bounds__(256, 2) gemm_mma(
    const bf16* __restrict__ Ah, const bf16* __restrict__ Al,
    const bf16* __restrict__ Bh, const bf16* __restrict__ Bl,
    const float* __restrict__ bias,
    float* __restrict__ C, bf16* __restrict__ Ch, bf16* __restrict__ Cl,
    int N, int K)
{
    gemm_body<MODE>(Ah, Al, Bh, Bl, bias, C, Ch, Cl, N, K, K, 0, 1.0f,
                    blockIdx.y * 128, blockIdx.x * 128);
}

// Split-K x3 (fp32 output): z=0 -> C0 (+bias), z=1 -> C1, z=2 -> C2.
__global__ void __launch_bounds__(256, 2) gemm_splitk(
    const bf16* __restrict__ Ah, const bf16* __restrict__ Al,
    const bf16* __restrict__ Bh, const bf16* __restrict__ Bl,
    const float* __restrict__ bias,
    float* __restrict__ C0, float* __restrict__ C1, float* __restrict__ C2,
    int N, int K)
{
    int z = blockIdx.z;
    int kh = K / 3;
    float* Cz = (z == 0) ? C0 : (z == 1) ? C1 : C2;
    gemm_body<0>(Ah, Al, Bh, Bl, z ? g_zero : bias, Cz,
                 nullptr, nullptr, N, K, kh, z * kh, 1.0f,
                 blockIdx.y * 128, blockIdx.x * 128);
}

// Combined QKV: blockIdx.z selects weight/bias/output.
// Q pre-scaled by 0.125 * log2(e) so attention runs in the exp2 domain.
#define QSCALE (0.125f * 1.4426950408889634f)
__global__ void __launch_bounds__(256, 2) gemm_qkv(
    const bf16* __restrict__ Ah, const bf16* __restrict__ Al,
    const bf16* __restrict__ Wqh, const bf16* __restrict__ Wql,
    const bf16* __restrict__ Wkh, const bf16* __restrict__ Wkl,
    const bf16* __restrict__ Wvh, const bf16* __restrict__ Wvl,
    const float* __restrict__ bq, const float* __restrict__ bk,
    const float* __restrict__ bv,
    bf16* __restrict__ qh, bf16* __restrict__ ql,
    bf16* __restrict__ kh, bf16* __restrict__ kl,
    bf16* __restrict__ vh, bf16* __restrict__ vl)
{
    int z = blockIdx.z;
    const bf16* Bh = (z == 0) ? Wqh : (z == 1) ? Wkh : Wvh;
    const bf16* Bl = (z == 0) ? Wql : (z == 1) ? Wkl : Wvl;
    const float* bias = (z == 0) ? bq : (z == 1) ? bk : bv;
    bf16* Ch = (z == 0) ? qh : (z == 1) ? kh : vh;
    bf16* Cl = (z == 0) ? ql : (z == 1) ? kl : vl;
    float scale = (z == 0) ? QSCALE : 1.0f;
    gemm_body<1>(Ah, Al, Bh, Bl, bias, nullptr, Ch, Cl,
                 DMODEL, DMODEL, DMODEL, 0, scale,
                 blockIdx.y * 128, blockIdx.x * 128);
}

// ---------------------------------------------------------------------------
// Flash attention via mma.sync bf16 hi/lo split; softmax in exp2 domain.
// ---------------------------------------------------------------------------
#define ASMEM_BYTES (32768 + 2*32768 + 1024)

__global__ void __launch_bounds__(256, 2) attn_mma(
    const bf16* __restrict__ Qh, const bf16* __restrict__ Ql,
    const bf16* __restrict__ Kh, const bf16* __restrict__ Kl,
    const bf16* __restrict__ Vh, const bf16* __restrict__ Vl,
    bf16* __restrict__ Oh, bf16* __restrict__ Ol)
{
    extern __shared__ __align__(1024) char smem_raw[];
    uint32_t sb = smem_u32(smem_raw);
    sb = (sb + 1023) & ~1023u;

    const int tid  = threadIdx.x;
    const int lane = tid & 31, wq = tid >> 5;
    const int l15 = lane & 15, lh = lane >> 4;
    const int g4 = lane >> 2, t4 = lane & 3;
    const int b = blockIdx.z, h = blockIdx.y;
    const int q0 = blockIdx.x * 128;
    const size_t hoff = (size_t)h * HDIM;

    {
        int qrow = tid >> 1;
        int cb = (tid & 1) * 4;
        size_t gidx = ((size_t)(b * SEQ + q0 + qrow)) * DMODEL + hoff;
        uint32_t st = sb + qrow * 128;
        #pragma unroll
        for (int c = 0; c < 4; c++) {
            uint32_t ph = (uint32_t)(((cb + c) ^ (qrow & 7)) << 4);
            CP16(st + ph,         Qh + gidx + (cb + c) * 8);
            CP16(st + 16384 + ph, Ql + gidx + (cb + c) * 8);
        }
    }
    CP_COMMIT();

    const int krow = tid >> 2;
    const int kc0  = (tid & 3) * 2;
    auto load_kv = [&](int s, int kt) {
        uint32_t base = sb + 32768 + s * 32768;
        size_t gidx = ((size_t)(b * SEQ + kt * 64 + krow)) * DMODEL + hoff;
        #pragma unroll
        for (int cc = 0; cc < 2; cc++) {
            int c = kc0 + cc;
            uint32_t off = krow * 128 + ((c ^ (krow & 7)) << 4);
            CP16(base + off,         Kh + gidx + c * 8);
            CP16(base + 8192 + off,  Kl + gidx + c * 8);
            CP16(base + 16384 + off, Vh + gidx + c * 8);
            CP16(base + 24576 + off, Vl + gidx + c * 8);
        }
    };
    load_kv(0, 0);
    CP_COMMIT();

    float m0 = -1e30f, m1 = -1e30f, l0 = 0.f, l1 = 0.f;
    float o[8][4];
    #pragma unroll
    for (int j = 0; j < 8; j++)
        #pragma unroll
        for (int q = 0; q < 4; q++) o[j][q] = 0.f;

    const int NT = SEQ / 64;
    for (int kt = 0; kt < NT; kt++) {
        CP_WAIT0();
        __syncthreads();
        if (kt + 1 < NT) {
            load_kv((kt + 1) & 1, kt + 1);
            CP_COMMIT();
        }

        uint32_t stb = sb + 32768 + (kt & 1) * 32768;

        float s[8][4];
        #pragma unroll
        for (int j = 0; j < 8; j++)
            #pragma unroll
            for (int q = 0; q < 4; q++) s[j][q] = 0.f;

        #pragma unroll
        for (int kc = 0; kc < 4; kc++) {
            const int chunk = kc * 2 + lh;
            int arow = wq * 16 + l15;
            uint32_t aaddr = sb + arow * 128 + ((chunk ^ (arow & 7)) << 4);
            uint32_t qh_[4], ql_[4];
            ldsm4(aaddr,         qh_[0], qh_[1], qh_[2], qh_[3]);
            ldsm4(aaddr + 16384, ql_[0], ql_[1], ql_[2], ql_[3]);
            #pragma unroll
            for (int g = 0; g < 4; g++) {
                int brow = g * 16 + l15;
                uint32_t baddr = stb + brow * 128 + ((chunk ^ (brow & 7)) << 4);
                uint32_t kh_[4], kl_[4];
                ldsm4(baddr,        kh_[0], kh_[1], kh_[2], kh_[3]);
                ldsm4(baddr + 8192, kl_[0], kl_[1], kl_[2], kl_[3]);
                mma16816(s[2*g],   qh_, kh_[0], kh_[2]);
                mma16816(s[2*g],   qh_, kl_[0], kl_[2]);
                mma16816(s[2*g],   ql_, kh_[0], kh_[2]);
                mma16816(s[2*g+1], qh_, kh_[1], kh_[3]);
                mma16816(s[2*g+1], qh_, kl_[1], kl_[3]);
                mma16816(s[2*g+1], ql_, kh_[1], kh_[3]);
            }
        }

        float mx0 = -1e30f, mx1 = -1e30f;
        #pragma unroll
        for (int j = 0; j < 8; j++) {
            mx0 = fmaxf(mx0, fmaxf(s[j][0], s[j][1]));
            mx1 = fmaxf(mx1, fmaxf(s[j][2], s[j][3]));
        }
        mx0 = fmaxf(mx0, __shfl_xor_sync(0xffffffffu, mx0, 1));
        mx0 = fmaxf(mx0, __shfl_xor_sync(0xffffffffu, mx0, 2));
        mx1 = fmaxf(mx1, __shfl_xor_sync(0xffffffffu, mx1, 1));
        mx1 = fmaxf(mx1, __shfl_xor_sync(0xffffffffu, mx1, 2));

        float mn0 = fmaxf(m0, mx0), mn1 = fmaxf(m1, mx1);
        float a0 = fexp2(m0 - mn0), a1 = fexp2(m1 - mn1);
        m0 = mn0; m1 = mn1;

        float sum0 = 0.f, sum1 = 0.f;
        #pragma unroll
        for (int j = 0; j < 8; j++) {
            s[j][0] = fexp2(s[j][0] - mn0);
            s[j][1] = fexp2(s[j][1] - mn0);
            s[j][2] = fexp2(s[j][2] - mn1);
            s[j][3] = fexp2(s[j][3] - mn1);
            sum0 += s[j][0] + s[j][1];
            sum1 += s[j][2] + s[j][3];
        }
        sum0 += __shfl_xor_sync(0xffffffffu, sum0, 1);
        sum0 += __shfl_xor_sync(0xffffffffu, sum0, 2);
        sum1 += __shfl_xor_sync(0xffffffffu, sum1, 1);
        sum1 += __shfl_xor_sync(0xffffffffu, sum1, 2);
        l0 = l0 * a0 + sum0;
        l1 = l1 * a1 + sum1;

        #pragma unroll
        for (int j = 0; j < 8; j++) {
            o[j][0] *= a0; o[j][1] *= a0;
            o[j][2] *= a1; o[j][3] *= a1;
        }

        #pragma unroll
        for (int kc = 0; kc < 4; kc++) {
            uint32_t ph_[4], pl_[4];
            split2(s[2*kc][0],   s[2*kc][1],   ph_[0], pl_[0]);
            split2(s[2*kc][2],   s[2*kc][3],   ph_[1], pl_[1]);
            split2(s[2*kc+1][0], s[2*kc+1][1], ph_[2], pl_[2]);
            split2(s[2*kc+1][2], s[2*kc+1][3], ph_[3], pl_[3]);

            int vrow = kc * 16 + (lane & 7) + ((lane >> 3) & 1) * 8;
            #pragma unroll
            for (int nn = 0; nn < 4; nn++) {
                int colchunk = nn * 2 + (lane >> 4);
                uint32_t vaddr = stb + 16384 + vrow * 128
                               + ((colchunk ^ (vrow & 7)) << 4);
                uint32_t vh_[4], vl_[4];
                ldsm4t(vaddr,        vh_[0], vh_[1], vh_[2], vh_[3]);
                ldsm4t(vaddr + 8192, vl_[0], vl_[1], vl_[2], vl_[3]);
                mma16816(o[2*nn],   ph_, vh_[0], vh_[1]);
                mma16816(o[2*nn],   ph_, vl_[0], vl_[1]);
                mma16816(o[2*nn],   pl_, vh_[0], vh_[1]);
                mma16816(o[2*nn+1], ph_, vh_[2], vh_[3]);
                mma16816(o[2*nn+1], ph_, vl_[2], vl_[3]);
                mma16816(o[2*nn+1], pl_, vh_[2], vh_[3]);
            }
        }
    }

    float i0 = 1.0f / l0, i1 = 1.0f / l1;
    int row0 = b * SEQ + q0 + wq * 16 + g4;
    #pragma unroll
    for (int j = 0; j < 8; j++) {
        int col = (int)hoff + j * 8 + t4 * 2;
        uint32_t h0, lo0, h1, lo1;
        split2(o[j][0] * i0, o[j][1] * i0, h0, lo0);
        split2(o[j][2] * i1, o[j][3] * i1, h1, lo1);
        *(uint32_t*)(Oh + (size_t)row0 * DMODEL + col)       = h0;
        *(uint32_t*)(Ol + (size_t)row0 * DMODEL + col)       = lo0;
        *(uint32_t*)(Oh + (size_t)(row0 + 8) * DMODEL + col) = h1;
        *(uint32_t*)(Ol + (size_t)(row0 + 8) * DMODEL + col) = lo1;
    }
}

// ---------------------------------------------------------------------------
// Fused residual add + LayerNorm over (y0 + y1 + y2 + residual).
// ---------------------------------------------------------------------------
__global__ void __launch_bounds__(256) ln_res_kernel(
    const float* __restrict__ y0, const float* __restrict__ y1,
    const float* __restrict__ y2, const float* __restrict__ r,
    const float* __restrict__ g, const float* __restrict__ b,
    float* __restrict__ o, bf16* __restrict__ oh, bf16* __restrict__ ol)
{
    const int row = blockIdx.x;
    const int tid = threadIdx.x;
    const float* y0p = y0 + (size_t)row * DMODEL;
    const float* y1p = y1 + (size_t)row * DMODEL;
    const float* y2p = y2 + (size_t)row * DMODEL;
    const float* rp  = r  + (size_t)row * DMODEL;

    float v[3];
    float s = 0.f, ss = 0.f;
    #pragma unroll
    for (int j = 0; j < 3; j++) {
        int c = tid + j * 256;
        float a = y0p[c] + y1p[c] + y2p[c] + rp[c];
        v[j] = a; s += a; ss += a * a;
    }
    #pragma unroll
    for (int off = 16; off; off >>= 1) {
        s  += __shfl_xor_sync(0xffffffffu, s, off);
        ss += __shfl_xor_sync(0xffffffffu, ss, off);
    }
    __shared__ float sred[16];
    if ((tid & 31) == 0) { sred[tid >> 5] = s; sred[8 + (tid >> 5)] = ss; }
    __syncthreads();
    if (tid == 0) {
        float S = 0.f, SS = 0.f;
        #pragma unroll
        for (int w = 0; w < 8; w++) { S += sred[w]; SS += sred[8 + w]; }
        sred[0] = S * (1.0f / DMODEL);
        sred[1] = SS * (1.0f / DMODEL);
    }
    __syncthreads();
    float mu  = sred[0];
    float var = sred[1] - mu * mu;
    float rstd = rsqrtf(var + 1e-5f);
    float* op = o + (size_t)row * DMODEL;
    #pragma unroll
    for (int j = 0; j < 3; j++) {
        int c = tid + j * 256;
        float val = (v[j] - mu) * rstd * g[c] + b[c];
        op[c] = val;
        if (oh) {
            bf16 hv = __float2bfloat16(val);
            oh[(size_t)row * DMODEL + c] = hv;
            ol[(size_t)row * DMODEL + c] =
                __float2bfloat16(val - __bfloat162float(hv));
        }
    }
}

// ---------------------------------------------------------------------------
extern "C" void kernel_launch(void* const* d_in, const int* in_sizes, int n_in,
                              void* d_out, int out_size)
{
    const float* x     = (const float*)d_in[0];
    const float* Wq    = (const float*)d_in[1];
    const float* bq    = (const float*)d_in[2];
    const float* Wk    = (const float*)d_in[3];
    const float* bk    = (const float*)d_in[4];
    const float* Wv    = (const float*)d_in[5];
    const float* bv    = (const float*)d_in[6];
    const float* Wo    = (const float*)d_in[7];
    const float* bo    = (const float*)d_in[8];
    const float* ln1g  = (const float*)d_in[9];
    const float* ln1b  = (const float*)d_in[10];
    const float* ln2g  = (const float*)d_in[11];
    const float* ln2b  = (const float*)d_in[12];
    const float* W1    = (const float*)d_in[13];
    const float* b1    = (const float*)d_in[14];
    const float* W2    = (const float*)d_in[15];
    const float* b2    = (const float*)d_in[16];
    float* out = (float*)d_out;

    float *p, *p2, *p3, *x1, *f, *f2, *f3;
    cudaGetSymbolAddress((void**)&p,  g_p);
    cudaGetSymbolAddress((void**)&p2, g_p2);
    cudaGetSymbolAddress((void**)&p3, g_p3);
    cudaGetSymbolAddress((void**)&x1, g_x1);
    cudaGetSymbolAddress((void**)&f,  g_f);
    cudaGetSymbolAddress((void**)&f2, g_f2);
    cudaGetSymbolAddress((void**)&f3, g_f3);

    bf16 *xh,*xl,*qh,*ql,*kh,*kl,*vh,*vl,*ah,*al,*x1h,*x1l,*hh,*hl;
    bf16 *Wqh,*Wql,*Wkh,*Wkl,*Wvh,*Wvl,*Woh,*Wol,*W1h,*W1l,*W2h,*W2l;
    cudaGetSymbolAddress((void**)&xh,  g_xh);  cudaGetSymbolAddress((void**)&xl,  g_xl);
    cudaGetSymbolAddress((void**)&qh,  g_qh);  cudaGetSymbolAddress((void**)&ql,  g_ql);
    cudaGetSymbolAddress((void**)&kh,  g_kh);  cudaGetSymbolAddress((void**)&kl,  g_kl);
    cudaGetSymbolAddress((void**)&vh,  g_vh);  cudaGetSymbolAddress((void**)&vl,  g_vl);
    cudaGetSymbolAddress((void**)&ah,  g_ah);  cudaGetSymbolAddress((void**)&al,  g_al);
    cudaGetSymbolAddress((void**)&x1h, g_x1h); cudaGetSymbolAddress((void**)&x1l, g_x1l);
    cudaGetSymbolAddress((void**)&hh,  g_hh);  cudaGetSymbolAddress((void**)&hl,  g_hl);
    cudaGetSymbolAddress((void**)&Wqh, g_Wqh); cudaGetSymbolAddress((void**)&Wql, g_Wql);
    cudaGetSymbolAddress((void**)&Wkh, g_Wkh); cudaGetSymbolAddress((void**)&Wkl, g_Wkl);
    cudaGetSymbolAddress((void**)&Wvh, g_Wvh); cudaGetSymbolAddress((void**)&Wvl, g_Wvl);
    cudaGetSymbolAddress((void**)&Woh, g_Woh); cudaGetSymbolAddress((void**)&Wol, g_Wol);
    cudaGetSymbolAddress((void**)&W1h, g_W1h); cudaGetSymbolAddress((void**)&W1l, g_W1l);
    cudaGetSymbolAddress((void**)&W2h, g_W2h); cudaGetSymbolAddress((void**)&W2l, g_W2l);

    cudaFuncSetAttribute(gemm_mma<2>,
                         cudaFuncAttributeMaxDynamicSharedMemorySize, GSMEM_BYTES);
    cudaFuncSetAttribute(gemm_splitk,
                         cudaFuncAttributeMaxDynamicSharedMemorySize, GSMEM_BYTES);
    cudaFuncSetAttribute(gemm_qkv,
                         cudaFuncAttributeMaxDynamicSharedMemorySize, GSMEM_BYTES);
    cudaFuncSetAttribute(attn_mma,
                         cudaFuncAttributeMaxDynamicSharedMemorySize, ASMEM_BYTES);

    dim3 blk(256);

    // Merged split conversion, MLP=4
    cvt_all_kernel<<<CB_TOTAL, blk>>>(x, Wq, Wk, Wv, Wo, W1, W2,
                                      xh, xl, Wqh, Wql, Wkh, Wkl, Wvh, Wvl,
                                      Woh, Wol, W1h, W1l, W2h, W2l);

    // QKV combined (bf16 split out; Q pre-scaled by 0.125*log2e)
    dim3 gqkv(DMODEL / 128, NTOK / 128, 3);
    gemm_qkv<<<gqkv, blk, GSMEM_BYTES>>>(xh, xl, Wqh, Wql, Wkh, Wkl, Wvh, Wvl,
                                         bq, bk, bv, qh, ql, kh, kl, vh, vl);

    // Attention (exp2-domain flash attention)
    dim3 ga(SEQ / 128, NHEAD, BATCH);
    attn_mma<<<ga, blk, ASMEM_BYTES>>>(qh, ql, kh, kl, vh, vl, ah, al);

    // Output projection (split-K x3) + residual LN1
    dim3 gS(DMODEL / 128, NTOK / 128, 3);
    gemm_splitk<<<gS, blk, GSMEM_BYTES>>>(ah, al, Woh, Wol, bo, p, p2, p3,
                                          DMODEL, DMODEL);
    ln_res_kernel<<<NTOK, blk>>>(p, p2, p3, x, ln1g, ln1b, x1, x1h, x1l);

    // FFN1 (GELU, bf16 split hidden)
    dim3 gF(FFND / 128, NTOK / 128);
    gemm_mma<2><<<gF, blk, GSMEM_BYTES>>>(x1h, x1l, W1h, W1l, b1,
                                          nullptr, hh, hl, FFND, DMODEL);
    // FFN2 (split-K x3) + residual LN2 -> out
    gemm_splitk<<<gS, blk, GSMEM_BYTES>>>(hh, hl, W2h, W2l, b2, f, f2, f3,
                                          DMODEL, FFND);
    ln_res_kernel<<<NTOK, blk>>>(f, f2, f3, x1, ln2g, ln2b, out, nullptr, nullptr);
}